// round 9
// baseline (speedup 1.0000x reference)
#include <cuda_runtime.h>
#include <cuda_bf16.h>
#include <math.h>

#define B_  32
#define T_  256
#define D_  1024
#define D3_ 3072
#define TB_ 8192
#define L_  2
#define NCTA_ 128

__device__ __nv_bfloat16 g_Wih_bf[2*L_*D3_*D_];
__device__ __nv_bfloat16 g_x_bf [TB_*D_];
__device__ __nv_bfloat16 g_yf_bf[TB_*D_];
__device__ __nv_bfloat16 g_yb_bf[TB_*D_];
__device__ float         g_xg[2][TB_*D3_];
__device__ __nv_bfloat16 g_hbf[2][2*B_*D_];
__device__ float         g_outvals[TB_];

__device__ unsigned g_flag[2][64][32];
__device__ unsigned g_barc2[2*32];
__device__ unsigned g_barg2[2*32];

#define MMA_BF16(d, a0,a1,a2,a3, b0,b1) \
  asm volatile("mma.sync.aligned.m16n8k16.row.col.f32.bf16.bf16.f32 " \
    "{%0,%1,%2,%3},{%4,%5,%6,%7},{%8,%9},{%0,%1,%2,%3};\n" \
    : "+f"(d[0]), "+f"(d[1]), "+f"(d[2]), "+f"(d[3]) \
    : "r"(a0), "r"(a1), "r"(a2), "r"(a3), "r"(b0), "r"(b1))

__device__ __forceinline__ void ldsm4(unsigned* r, unsigned a) {
  asm volatile("ldmatrix.sync.aligned.m8n8.x4.shared.b16 {%0,%1,%2,%3}, [%4];"
    : "=r"(r[0]), "=r"(r[1]), "=r"(r[2]), "=r"(r[3]) : "r"(a));
}
__device__ __forceinline__ void cpasync16(unsigned dst, const void* src) {
  asm volatile("cp.async.cg.shared.global [%0], [%1], 16;" :: "r"(dst), "l"(src));
}
#define CP_COMMIT() asm volatile("cp.async.commit_group;" ::: "memory")
#define CP_WAIT(n)  asm volatile("cp.async.wait_group %0;" :: "n"(n) : "memory")
#define BAR_SYNC(id,cnt) asm volatile("bar.sync %0,%1;"::"r"(id),"r"(cnt):"memory")
#define BAR_ARR(id,cnt)  asm volatile("bar.arrive %0,%1;"::"r"(id),"r"(cnt):"memory")

__device__ __forceinline__ unsigned ld_acq(const unsigned* p) {
  unsigned v;
  asm volatile("ld.acquire.gpu.global.u32 %0, [%1];" : "=r"(v) : "l"(p));
  return v;
}
__device__ __forceinline__ void st_rel(unsigned* p, unsigned v) {
  asm volatile("st.release.gpu.global.u32 [%0], %1;" :: "l"(p), "r"(v));
}
__device__ __forceinline__ float fast_tanh(float x) {
  float xc = fminf(fmaxf(x, -30.f), 30.f);
  float e = __expf(-2.f*xc);
  return (1.f - e) * __frcp_rn(1.f + e);
}
__device__ __forceinline__ void gridbar2(int s, unsigned nc) {
  __syncthreads();
  if (threadIdx.x == 0) {
    __threadfence();
    volatile unsigned* genp = (volatile unsigned*)&g_barg2[s*32];
    unsigned gen = *genp;
    if (atomicAdd(&g_barc2[s*32], 1u) == nc - 1u) {
      g_barc2[s*32] = 0;
      __threadfence();
      *genp = gen + 1;
    } else {
      while (*genp == gen) { }
      __threadfence();
    }
  }
  __syncthreads();
}

__global__ void k_convw(const float* __restrict__ Wih_f, const float* __restrict__ Wih_b) {
  const int N = L_*D3_*D_;
  for (int i = blockIdx.x*blockDim.x + threadIdx.x; i < N; i += gridDim.x*blockDim.x) {
    g_Wih_bf[i]     = __float2bfloat16(Wih_f[i]);
    g_Wih_bf[N + i] = __float2bfloat16(Wih_b[i]);
  }
}

__global__ __launch_bounds__(256) void k_proj(const float* __restrict__ input, const float* __restrict__ cond,
    const float* __restrict__ Wc, const float* __restrict__ bc,
    const float* __restrict__ Wi, const float* __restrict__ bi) {
  int t = blockIdx.x;
  int tid = threadIdx.x;
  __shared__ float cond_s[B_][80];
  __shared__ float in_s[B_][72];
  __shared__ float wbuf[64][80];
  __shared__ float bias_s[64];
  for (int i = tid; i < B_*80; i += 256) {
    int b = i / 80, j = i % 80;
    cond_s[b][j] = cond[((size_t)b*T_ + t)*80 + j];
  }
  for (int i = tid; i < B_*72; i += 256) {
    int b = i / 72, j = i % 72;
    in_s[b][j] = input[((size_t)b*T_ + t)*72 + j];
  }
  __syncthreads();
  for (int chunk = 0; chunk < 16; chunk++) {
    int dbase = chunk*64;
    int width = (dbase < 512) ? 80 : 72;
    const float* Wsrc = (dbase < 512) ? (Wc + (size_t)dbase*80) : (Wi + (size_t)(dbase-512)*72);
    for (int i = tid; i < 64*width; i += 256) wbuf[i/width][i%width] = Wsrc[i];
    if (tid < 64) bias_s[tid] = (dbase < 512) ? bc[dbase+tid] : bi[dbase-512+tid];
    __syncthreads();
    for (int i = tid; i < B_*64; i += 256) {
      int b = i & 31, dd = i >> 5;
      const float* act = (dbase < 512) ? &cond_s[b][0] : &in_s[b][0];
      float a = bias_s[dd];
      const float* w = &wbuf[dd][0];
      #pragma unroll 8
      for (int j = 0; j < width; j++) a += w[j]*act[j];
      a = fmaxf(a, 0.f);
      g_x_bf[((size_t)t*B_ + b)*D_ + dbase + dd] = __float2bfloat16(a);
    }
    __syncthreads();
  }
}

__global__ __launch_bounds__(256) void k_gemm(int layer,
    const float* __restrict__ bih_f, const float* __restrict__ bih_b) {
  int dir = blockIdx.z;
  const __nv_bfloat16* A = (layer == 0) ? g_x_bf : (dir ? g_yb_bf : g_yf_bf);
  const __nv_bfloat16* W = g_Wih_bf + (size_t)(dir*L_ + layer)*D3_*D_;
  const float* bias = (dir ? bih_b : bih_f) + (size_t)layer*D3_;
  float* C = g_xg[dir];
  int m0 = blockIdx.y*128, n0 = blockIdx.x*64;

  __shared__ alignas(16) __nv_bfloat16 As[2][128][40];
  __shared__ alignas(16) __nv_bfloat16 Bs[2][64][40];

  int tid = threadIdx.x, lane = tid&31, warp = tid>>5;
  int wm = warp>>1, wn = warp&1, tg = lane>>2, tc = lane&3;
  int lr = tid>>2, lc = (tid&3)*8;

  float acc[2][4][4];
  #pragma unroll
  for (int i=0;i<2;i++)
    #pragma unroll
    for(int j=0;j<4;j++)
      #pragma unroll
      for(int k=0;k<4;k++) acc[i][j][k]=0.f;

  uint4 va0, va1, vb0;
  va0 = *(const uint4*)&A[(size_t)(m0+lr)*D_ + lc];
  va1 = *(const uint4*)&A[(size_t)(m0+lr+64)*D_ + lc];
  vb0 = *(const uint4*)&W[(size_t)(n0+lr)*D_ + lc];
  *(uint4*)&As[0][lr][lc]    = va0;
  *(uint4*)&As[0][lr+64][lc] = va1;
  *(uint4*)&Bs[0][lr][lc]    = vb0;
  __syncthreads();

  int cur = 0;
  for (int it = 0; it < 32; it++) {
    if (it < 31) {
      int kc = (it+1)*32;
      va0 = *(const uint4*)&A[(size_t)(m0+lr)*D_ + kc + lc];
      va1 = *(const uint4*)&A[(size_t)(m0+lr+64)*D_ + kc + lc];
      vb0 = *(const uint4*)&W[(size_t)(n0+lr)*D_ + kc + lc];
    }
    #pragma unroll
    for (int s = 0; s < 32; s += 16) {
      unsigned a[2][4];
      #pragma unroll
      for (int mt = 0; mt < 2; mt++) {
        int r = wm*32 + mt*16 + tg;
        a[mt][0] = *(const unsigned*)&As[cur][r  ][s + 2*tc];
        a[mt][1] = *(const unsigned*)&As[cur][r+8][s + 2*tc];
        a[mt][2] = *(const unsigned*)&As[cur][r  ][s + 2*tc + 8];
        a[mt][3] = *(const unsigned*)&As[cur][r+8][s + 2*tc + 8];
      }
      #pragma unroll
      for (int nt = 0; nt < 4; nt++) {
        int nr = wn*32 + nt*8 + tg;
        unsigned b0 = *(const unsigned*)&Bs[cur][nr][s + 2*tc];
        unsigned b1 = *(const unsigned*)&Bs[cur][nr][s + 2*tc + 8];
        MMA_BF16(acc[0][nt], a[0][0],a[0][1],a[0][2],a[0][3], b0, b1);
        MMA_BF16(acc[1][nt], a[1][0],a[1][1],a[1][2],a[1][3], b0, b1);
      }
    }
    if (it < 31) {
      int nxt = cur^1;
      *(uint4*)&As[nxt][lr][lc]    = va0;
      *(uint4*)&As[nxt][lr+64][lc] = va1;
      *(uint4*)&Bs[nxt][lr][lc]    = vb0;
    }
    __syncthreads();
    cur ^= 1;
  }

  #pragma unroll
  for (int mt=0; mt<2; mt++) {
    #pragma unroll
    for (int nt=0; nt<4; nt++) {
      int gr = m0 + wm*32 + mt*16 + tg;
      int gc = n0 + wn*32 + nt*8 + 2*tc;
      C[(size_t)gr*D3_ + gc]       = acc[mt][nt][0] + bias[gc];
      C[(size_t)gr*D3_ + gc + 1]   = acc[mt][nt][1] + bias[gc+1];
      C[(size_t)(gr+8)*D3_ + gc]   = acc[mt][nt][2] + bias[gc];
      C[(size_t)(gr+8)*D3_ + gc+1] = acc[mt][nt][3] + bias[gc+1];
    }
  }
}

// persistent recurrence: 512 thr = 12 MMA warps (wk=warp&3, wn=warp>>2) + 4 loader warps.
// ready bars 1+c (128), free bars 9+c (128), 13 partials (384), 14 gate (256).
// loaders also cp.async the xg(t+1) tile (no flag dependency) in sub-chunk 0's group.
#define HS_STRIDE 1032
#define OFF_WS   66048
#define OFF_XG   (OFF_WS + 99072)
#define OFF_HGP  (OFF_XG + 12288)
#define OFF_BHH  (OFF_HGP + 50176)
#define RNN_SMEM (OFF_BHH + 192)

__global__ __launch_bounds__(512, 1) void k_rnn(int layer,
    const float* __restrict__ Whh_f, const float* __restrict__ Whh_b,
    const float* __restrict__ bhh_f, const float* __restrict__ bhh_b) {
  extern __shared__ char smem_raw[];
  __nv_bfloat16* hs  = (__nv_bfloat16*)smem_raw;                 // [32][1032]
  __nv_bfloat16* Ws  = (__nv_bfloat16*)(smem_raw + OFF_WS);      // [48][1032]
  float*         xg_s= (float*)(smem_raw + OFF_XG);              // [2][32][48]
  float*         hgp = (float*)(smem_raw + OFF_HGP);             // [2][32][196]
  float*         bhh_s=(float*)(smem_raw + OFF_BHH);             // [48]

  int stack = blockIdx.x >> 6;
  int blk   = blockIdx.x & 63;
  int cgb   = blk * 16;
  const float* Whh = (stack ? Whh_b : Whh_f) + (size_t)layer*D3_*D_;
  const float* xg = g_xg[stack];
  const float* bhh = (stack ? bhh_b : bhh_f) + (size_t)layer*D3_;
  __nv_bfloat16* ys = stack ? g_yb_bf : g_yf_bf;

  int tid = threadIdx.x, lane = tid&31, warp = tid>>5;
  int wk = warp & 3, wn = warp >> 2;
  int tg = lane>>2, tc = lane&3;

  for (int i = tid; i < 12288; i += 512) {
    int row = i >> 8, q4 = (i & 255) * 4;
    size_t grow = (size_t)((row >> 4)*D_ + cgb + (row & 15));
    float4 v = *(const float4*)&Whh[grow*D_ + q4];
    __nv_bfloat16 b4[4] = { __float2bfloat16(v.x), __float2bfloat16(v.y),
                            __float2bfloat16(v.z), __float2bfloat16(v.w) };
    *(uint2*)&Ws[row*HS_STRIDE + q4] = *(uint2*)b4;
  }
  for (int i = tid; i < 48; i += 512)
    bhh_s[i] = bhh[(i>>4)*D_ + cgb + (i&15)];
  {
    uint4 z = make_uint4(0,0,0,0);
    for (int i = tid; i < 4096; i += 512) {
      int b = i >> 7, c8 = (i & 127) * 8;
      *(uint4*)&hs[b*HS_STRIDE + c8] = z;
    }
  }
  // commit xg(t=0) into buffer 0 (threads 0..383, one uint4 each)
  if (tid < 384) {
    int pb = tid / 12, prem = tid % 12, pg = prem >> 2, pq = prem & 3;
    uint4 v = *(const uint4*)&xg[(size_t)pb*D3_ + (size_t)pg*D_ + cgb + pq*4];
    *(uint4*)&xg_s[pb*48 + pg*16 + pq*4] = v;
  }
  if (tid == 0) g_flag[stack][blk][0] = 0;
  gridbar2(stack, 64);

  unsigned hs_sm = (unsigned)__cvta_generic_to_shared(hs);
  unsigned ws_sm = (unsigned)__cvta_generic_to_shared(Ws);
  unsigned xg_sm = (unsigned)__cvta_generic_to_shared(xg_s);

  if (warp >= 12) {
    // ---------------- loader warp c ----------------
    int c = warp - 12;
    const size_t stk = (size_t)stack*B_*D_;
    // per-lane xg cp.async mapping: 3 uint4 per lane, 128 lanes cover 384
    int q = c*32 + lane;
    size_t xsrcoff[3]; unsigned xdstoff[3];
    #pragma unroll
    for (int k = 0; k < 3; k++) {
      int u = q*3 + k;
      int b = u / 12, rem = u % 12, g = rem >> 2, q4 = rem & 3;
      xsrcoff[k] = (size_t)b*D3_ + (size_t)g*D_ + cgb + q4*4;
      xdstoff[k] = 4u*(unsigned)(b*48 + g*16 + q4*4);
    }
    for (int j = 0; j < T_ - 1; j++) {
      BAR_SYNC(9 + c, 128);                       // hs(t=j) consumed by group c
      const __nv_bfloat16* hin = g_hbf[(j + 1) & 1] + stk;
      unsigned want = (unsigned)(j + 1);
      // xg(t=j+1) prefetch (no flag dependency) — joins sub-chunk 0's group
      {
        const float* xsrc = xg + (size_t)(j + 1)*B_*D3_;
        unsigned xdst = xg_sm + (unsigned)(((j + 1) & 1) * 6144);
        cpasync16(xdst + xdstoff[0], xsrc + xsrcoff[0]);
        cpasync16(xdst + xdstoff[1], xsrc + xsrcoff[1]);
        cpasync16(xdst + xdstoff[2], xsrc + xsrcoff[2]);
      }
      #define POLLS(s) do { \
        const unsigned* fps = &g_flag[stack][c*16 + (s)*4 + (lane & 3)][0]; \
        unsigned v = (lane < 4) ? ld_acq(fps) : 0xffffffffu; \
        while (!__all_sync(0xffffffffu, v >= want)) \
          v = (lane < 4) ? ld_acq(fps) : 0xffffffffu; \
      } while (0)
      #define ISSUES(s) do { \
        int base = c*256 + (s)*64; \
        _Pragma("unroll") \
        for (int it2 = 0; it2 < 8; it2++) { \
          int i2 = lane + it2*32; \
          int b2 = i2 >> 3, q2 = (i2 & 7)*8; \
          cpasync16(hs_sm + 2u*(unsigned)(b2*HS_STRIDE + base + q2), \
                    hin + (size_t)b2*D_ + base + q2); \
        } \
        CP_COMMIT(); \
      } while (0)
      POLLS(0); ISSUES(0);
      POLLS(1); ISSUES(1);
      CP_WAIT(1); BAR_ARR(1 + c, 128);
      POLLS(2); ISSUES(2);
      CP_WAIT(1); BAR_ARR(1 + c, 128);
      POLLS(3); ISSUES(3);
      CP_WAIT(1); BAR_ARR(1 + c, 128);
      CP_WAIT(0); BAR_ARR(1 + c, 128);
      #undef POLLS
      #undef ISSUES
    }
    BAR_SYNC(9 + c, 128);                         // balance t=T-1 free arrivals
  } else {
    // ---------------- MMA (+gate) warps ----------------
    int gb = tid >> 3, jp = tid & 7;              // gate: batch gb, cols 2jp, 2jp+1
    unsigned* myflag = &g_flag[stack][blk][0];

    unsigned aBase0 = hs_sm + 2u*((lane&15)*HS_STRIDE + ((lane>>4)*8) + wk*256);
    unsigned aBase1 = aBase0 + 2u*16*HS_STRIDE;
    unsigned bBase  = ws_sm + 2u*((wn*16 + (lane&7) + ((lane>>4)*8))*HS_STRIDE
                                + (((lane>>3)&1)*8) + wk*256);
    float hp0 = 0.f, hp1 = 0.f;

    for (int t = 0; t < T_; t++) {
      int buf = t & 1;
      float* xgb = xg_s + buf*1536;
      float* hgb = hgp  + buf*6272;

      float acc[2][2][4];
      #pragma unroll
      for (int i=0;i<2;i++)
        #pragma unroll
        for (int j2=0;j2<2;j2++)
          #pragma unroll
          for (int q=0;q<4;q++) acc[i][j2][q]=0.f;

      #pragma unroll
      for (int s = 0; s < 4; s++) {
        if (t > 0) BAR_SYNC(1 + wk, 128);         // sub-chunk s of h(t) ready
        unsigned a0A = aBase0 + 128u*s, a1A = aBase1 + 128u*s, bA = bBase + 128u*s;
        #pragma unroll
        for (int kt = 0; kt < 4; kt++) {
          unsigned fa0[4], fa1[4], fb[4];
          ldsm4(fa0, a0A); ldsm4(fa1, a1A); ldsm4(fb, bA);
          MMA_BF16(acc[0][0], fa0[0],fa0[1],fa0[2],fa0[3], fb[0], fb[1]);
          MMA_BF16(acc[0][1], fa0[0],fa0[1],fa0[2],fa0[3], fb[2], fb[3]);
          MMA_BF16(acc[1][0], fa1[0],fa1[1],fa1[2],fa1[3], fb[0], fb[1]);
          MMA_BF16(acc[1][1], fa1[0],fa1[1],fa1[2],fa1[3], fb[2], fb[3]);
          a0A += 32; a1A += 32; bA += 32;
        }
      }
      BAR_ARR(9 + wk, 128);                       // hs(t) consumed

      // stage partials: hgb[b][col][wk], row stride 196
      #pragma unroll
      for (int mf = 0; mf < 2; mf++) {
        #pragma unroll
        for (int nf = 0; nf < 2; nf++) {
          int r = mf*16 + tg;
          int col = wn*16 + nf*8 + 2*tc;
          hgb[r*196 + col*4 + wk]         = acc[mf][nf][0];
          hgb[r*196 + (col+1)*4 + wk]     = acc[mf][nf][1];
          hgb[(r+8)*196 + col*4 + wk]     = acc[mf][nf][2];
          hgb[(r+8)*196 + (col+1)*4 + wk] = acc[mf][nf][3];
        }
      }
      if (warp < 8) {
        BAR_SYNC(13, 384);
        __nv_bfloat16* hout = g_hbf[buf ^ 1] + (size_t)stack*B_*D_;
        #pragma unroll
        for (int half = 0; half < 2; half++) {
          int j = 2*jp + half;
          float4 pr = *(const float4*)&hgb[gb*196 + j*4];
          float4 pz = *(const float4*)&hgb[gb*196 + (16 + j)*4];
          float4 pn = *(const float4*)&hgb[gb*196 + (32 + j)*4];
          float xr = xgb[gb*48 + j];
          float xz = xgb[gb*48 + 16 + j];
          float xn = xgb[gb*48 + 32 + j];
          float hr = bhh_s[j]      + ((pr.x + pr.y) + (pr.z + pr.w));
          float hz = bhh_s[16 + j] + ((pz.x + pz.y) + (pz.z + pz.w));
          float hn = bhh_s[32 + j] + ((pn.x + pn.y) + (pn.z + pn.w));
          float r  = 1.f/(1.f + __expf(-(xr+hr)));
          float z  = 1.f/(1.f + __expf(-(xz+hz)));
          float nn = fast_tanh(xn + r*hn);
          float hprev = half ? hp1 : hp0;
          float hnew = (1.f - z)*nn + z*hprev;
          if (half) hp1 = hnew; else hp0 = hnew;
        }
        __nv_bfloat162 pk;
        pk.x = __float2bfloat16(hp0);
        pk.y = __float2bfloat16(hp1);
        *(__nv_bfloat162*)&hout[(size_t)gb*D_ + cgb + 2*jp] = pk;
        BAR_SYNC(14, 256);
        if (tid == 0) st_rel(myflag, (unsigned)(t + 1));
        *(__nv_bfloat162*)&ys[((size_t)t*B_ + gb)*D_ + cgb + 2*jp] = pk;
      } else {
        BAR_ARR(13, 384);
      }
    }
  }
}

__global__ __launch_bounds__(128) void k_out1(const float* __restrict__ Wo, const float* __restrict__ bo) {
  int row = blockIdx.x;
  int tid = threadIdx.x;
  float acc = 0.f;
  for (int d = tid; d < D_; d += 128)
    acc += (__bfloat162float(g_yf_bf[(size_t)row*D_+d]) +
            __bfloat162float(g_yb_bf[(size_t)row*D_+d])) * Wo[d];
  #pragma unroll
  for (int o = 16; o; o >>= 1) acc += __shfl_xor_sync(0xffffffffu, acc, o);
  __shared__ float ws[4];
  if ((tid & 31) == 0) ws[tid>>5] = acc;
  __syncthreads();
  if (tid == 0) {
    float s = ws[0]+ws[1]+ws[2]+ws[3] + bo[0];
    g_outvals[row] = 1.f/(1.f + expf(-s));
  }
}

__global__ void k_out2(float* out) {
  __shared__ float sm[256];
  int tid = threadIdx.x;
  float s = 0.f;
  for (int i = tid; i < TB_; i += 256) s += g_outvals[i];
  sm[tid] = s;
  __syncthreads();
  for (int o = 128; o; o >>= 1) { if (tid < o) sm[tid] += sm[tid+o]; __syncthreads(); }
  if (tid == 0) out[0] = sm[0] / (float)TB_;
}

extern "C" void kernel_launch(void* const* d_in, const int* in_sizes, int n_in,
                              void* d_out, int out_size) {
  (void)in_sizes; (void)n_in; (void)out_size;
  const float* input = (const float*)d_in[0];
  const float* cond  = (const float*)d_in[1];
  const float* Wc    = (const float*)d_in[2];
  const float* bc    = (const float*)d_in[3];
  const float* Wi    = (const float*)d_in[4];
  const float* bi    = (const float*)d_in[5];
  const float* Wih_f = (const float*)d_in[6];
  const float* Whh_f = (const float*)d_in[7];
  const float* bih_f = (const float*)d_in[8];
  const float* bhh_f = (const float*)d_in[9];
  const float* Wih_b = (const float*)d_in[10];
  const float* Whh_b = (const float*)d_in[11];
  const float* bih_b = (const float*)d_in[12];
  const float* bhh_b = (const float*)d_in[13];
  const float* Wo    = (const float*)d_in[14];
  const float* bo    = (const float*)d_in[15];
  float* out = (float*)d_out;

  cudaFuncSetAttribute(k_rnn, cudaFuncAttributeMaxDynamicSharedMemorySize, RNN_SMEM);

  k_convw<<<4096, 256>>>(Wih_f, Wih_b);
  k_proj<<<256, 256>>>(input, cond, Wc, bc, Wi, bi);
  for (int l = 0; l < L_; l++) {
    k_gemm<<<dim3(48, 64, 2), 256>>>(l, bih_f, bih_b);
    k_rnn<<<NCTA_, 512, RNN_SMEM>>>(l, Whh_f, Whh_b, bhh_f, bhh_b);
  }
  k_out1<<<TB_, 128>>>(Wo, bo);
  k_out2<<<1, 256>>>(out);
}

// round 11
// speedup vs baseline: 1.0034x; 1.0034x over previous
#include <cuda_runtime.h>
#include <cuda_bf16.h>
#include <math.h>

#define B_  32
#define T_  256
#define D_  1024
#define D3_ 3072
#define TB_ 8192
#define L_  2
#define NCTA_ 128

__device__ __nv_bfloat16 g_Wih_bf[2*L_*D3_*D_];
__device__ __nv_bfloat16 g_x_bf [TB_*D_];
__device__ __nv_bfloat16 g_yf_bf[TB_*D_];
__device__ __nv_bfloat16 g_yb_bf[TB_*D_];
__device__ float         g_xg[2][TB_*D3_];
__device__ __nv_bfloat16 g_hbf[2][2*B_*D_];
__device__ float         g_outvals[TB_];

__device__ unsigned g_flag[2][64][32];
__device__ unsigned g_barc2[2*32];
__device__ unsigned g_barg2[2*32];

#define MMA_BF16(d, a0,a1,a2,a3, b0,b1) \
  asm volatile("mma.sync.aligned.m16n8k16.row.col.f32.bf16.bf16.f32 " \
    "{%0,%1,%2,%3},{%4,%5,%6,%7},{%8,%9},{%0,%1,%2,%3};\n" \
    : "+f"(d[0]), "+f"(d[1]), "+f"(d[2]), "+f"(d[3]) \
    : "r"(a0), "r"(a1), "r"(a2), "r"(a3), "r"(b0), "r"(b1))

__device__ __forceinline__ void ldsm4(unsigned* r, unsigned a) {
  asm volatile("ldmatrix.sync.aligned.m8n8.x4.shared.b16 {%0,%1,%2,%3}, [%4];"
    : "=r"(r[0]), "=r"(r[1]), "=r"(r[2]), "=r"(r[3]) : "r"(a));
}
__device__ __forceinline__ void cpasync16(unsigned dst, const void* src) {
  asm volatile("cp.async.cg.shared.global [%0], [%1], 16;" :: "r"(dst), "l"(src));
}
#define CP_COMMIT() asm volatile("cp.async.commit_group;" ::: "memory")
#define CP_WAIT(n)  asm volatile("cp.async.wait_group %0;" :: "n"(n) : "memory")
#define BAR_SYNC(id,cnt) asm volatile("bar.sync %0,%1;"::"r"(id),"r"(cnt):"memory")
#define BAR_ARR(id,cnt)  asm volatile("bar.arrive %0,%1;"::"r"(id),"r"(cnt):"memory")

__device__ __forceinline__ unsigned ld_acq(const unsigned* p) {
  unsigned v;
  asm volatile("ld.acquire.gpu.global.u32 %0, [%1];" : "=r"(v) : "l"(p));
  return v;
}
__device__ __forceinline__ void st_rel(unsigned* p, unsigned v) {
  asm volatile("st.release.gpu.global.u32 [%0], %1;" :: "l"(p), "r"(v));
}
__device__ __forceinline__ unsigned ld_acq_sh(unsigned a) {
  unsigned v;
  asm volatile("ld.acquire.cta.shared.u32 %0, [%1];" : "=r"(v) : "r"(a));
  return v;
}
__device__ __forceinline__ void st_rel_sh(unsigned a, unsigned v) {
  asm volatile("st.release.cta.shared.u32 [%0], %1;" :: "r"(a), "r"(v));
}
__device__ __forceinline__ float fast_tanh(float x) {
  float xc = fminf(fmaxf(x, -30.f), 30.f);
  float e = __expf(-2.f*xc);
  return (1.f - e) * __frcp_rn(1.f + e);
}
__device__ __forceinline__ void gridbar2(int s, unsigned nc) {
  __syncthreads();
  if (threadIdx.x == 0) {
    __threadfence();
    volatile unsigned* genp = (volatile unsigned*)&g_barg2[s*32];
    unsigned gen = *genp;
    if (atomicAdd(&g_barc2[s*32], 1u) == nc - 1u) {
      g_barc2[s*32] = 0;
      __threadfence();
      *genp = gen + 1;
    } else {
      while (*genp == gen) { }
      __threadfence();
    }
  }
  __syncthreads();
}

__global__ void k_convw(const float* __restrict__ Wih_f, const float* __restrict__ Wih_b) {
  const int N = L_*D3_*D_;
  for (int i = blockIdx.x*blockDim.x + threadIdx.x; i < N; i += gridDim.x*blockDim.x) {
    g_Wih_bf[i]     = __float2bfloat16(Wih_f[i]);
    g_Wih_bf[N + i] = __float2bfloat16(Wih_b[i]);
  }
}

__global__ __launch_bounds__(256) void k_proj(const float* __restrict__ input, const float* __restrict__ cond,
    const float* __restrict__ Wc, const float* __restrict__ bc,
    const float* __restrict__ Wi, const float* __restrict__ bi) {
  int t = blockIdx.x;
  int tid = threadIdx.x;
  __shared__ float cond_s[B_][80];
  __shared__ float in_s[B_][72];
  __shared__ float wbuf[64][80];
  __shared__ float bias_s[64];
  for (int i = tid; i < B_*80; i += 256) {
    int b = i / 80, j = i % 80;
    cond_s[b][j] = cond[((size_t)b*T_ + t)*80 + j];
  }
  for (int i = tid; i < B_*72; i += 256) {
    int b = i / 72, j = i % 72;
    in_s[b][j] = input[((size_t)b*T_ + t)*72 + j];
  }
  __syncthreads();
  for (int chunk = 0; chunk < 16; chunk++) {
    int dbase = chunk*64;
    int width = (dbase < 512) ? 80 : 72;
    const float* Wsrc = (dbase < 512) ? (Wc + (size_t)dbase*80) : (Wi + (size_t)(dbase-512)*72);
    for (int i = tid; i < 64*width; i += 256) wbuf[i/width][i%width] = Wsrc[i];
    if (tid < 64) bias_s[tid] = (dbase < 512) ? bc[dbase+tid] : bi[dbase-512+tid];
    __syncthreads();
    for (int i = tid; i < B_*64; i += 256) {
      int b = i & 31, dd = i >> 5;
      const float* act = (dbase < 512) ? &cond_s[b][0] : &in_s[b][0];
      float a = bias_s[dd];
      const float* w = &wbuf[dd][0];
      #pragma unroll 8
      for (int j = 0; j < width; j++) a += w[j]*act[j];
      a = fmaxf(a, 0.f);
      g_x_bf[((size_t)t*B_ + b)*D_ + dbase + dd] = __float2bfloat16(a);
    }
    __syncthreads();
  }
}

__global__ __launch_bounds__(256) void k_gemm(int layer,
    const float* __restrict__ bih_f, const float* __restrict__ bih_b) {
  int dir = blockIdx.z;
  const __nv_bfloat16* A = (layer == 0) ? g_x_bf : (dir ? g_yb_bf : g_yf_bf);
  const __nv_bfloat16* W = g_Wih_bf + (size_t)(dir*L_ + layer)*D3_*D_;
  const float* bias = (dir ? bih_b : bih_f) + (size_t)layer*D3_;
  float* C = g_xg[dir];
  int m0 = blockIdx.y*128, n0 = blockIdx.x*64;

  __shared__ alignas(16) __nv_bfloat16 As[2][128][40];
  __shared__ alignas(16) __nv_bfloat16 Bs[2][64][40];

  int tid = threadIdx.x, lane = tid&31, warp = tid>>5;
  int wm = warp>>1, wn = warp&1, tg = lane>>2, tc = lane&3;
  int lr = tid>>2, lc = (tid&3)*8;

  float acc[2][4][4];
  #pragma unroll
  for (int i=0;i<2;i++)
    #pragma unroll
    for(int j=0;j<4;j++)
      #pragma unroll
      for(int k=0;k<4;k++) acc[i][j][k]=0.f;

  uint4 va0, va1, vb0;
  va0 = *(const uint4*)&A[(size_t)(m0+lr)*D_ + lc];
  va1 = *(const uint4*)&A[(size_t)(m0+lr+64)*D_ + lc];
  vb0 = *(const uint4*)&W[(size_t)(n0+lr)*D_ + lc];
  *(uint4*)&As[0][lr][lc]    = va0;
  *(uint4*)&As[0][lr+64][lc] = va1;
  *(uint4*)&Bs[0][lr][lc]    = vb0;
  __syncthreads();

  int cur = 0;
  for (int it = 0; it < 32; it++) {
    if (it < 31) {
      int kc = (it+1)*32;
      va0 = *(const uint4*)&A[(size_t)(m0+lr)*D_ + kc + lc];
      va1 = *(const uint4*)&A[(size_t)(m0+lr+64)*D_ + kc + lc];
      vb0 = *(const uint4*)&W[(size_t)(n0+lr)*D_ + kc + lc];
    }
    #pragma unroll
    for (int s = 0; s < 32; s += 16) {
      unsigned a[2][4];
      #pragma unroll
      for (int mt = 0; mt < 2; mt++) {
        int r = wm*32 + mt*16 + tg;
        a[mt][0] = *(const unsigned*)&As[cur][r  ][s + 2*tc];
        a[mt][1] = *(const unsigned*)&As[cur][r+8][s + 2*tc];
        a[mt][2] = *(const unsigned*)&As[cur][r  ][s + 2*tc + 8];
        a[mt][3] = *(const unsigned*)&As[cur][r+8][s + 2*tc + 8];
      }
      #pragma unroll
      for (int nt = 0; nt < 4; nt++) {
        int nr = wn*32 + nt*8 + tg;
        unsigned b0 = *(const unsigned*)&Bs[cur][nr][s + 2*tc];
        unsigned b1 = *(const unsigned*)&Bs[cur][nr][s + 2*tc + 8];
        MMA_BF16(acc[0][nt], a[0][0],a[0][1],a[0][2],a[0][3], b0, b1);
        MMA_BF16(acc[1][nt], a[1][0],a[1][1],a[1][2],a[1][3], b0, b1);
      }
    }
    if (it < 31) {
      int nxt = cur^1;
      *(uint4*)&As[nxt][lr][lc]    = va0;
      *(uint4*)&As[nxt][lr+64][lc] = va1;
      *(uint4*)&Bs[nxt][lr][lc]    = vb0;
    }
    __syncthreads();
    cur ^= 1;
  }

  #pragma unroll
  for (int mt=0; mt<2; mt++) {
    #pragma unroll
    for (int nt=0; nt<4; nt++) {
      int gr = m0 + wm*32 + mt*16 + tg;
      int gc = n0 + wn*32 + nt*8 + 2*tc;
      C[(size_t)gr*D3_ + gc]       = acc[mt][nt][0] + bias[gc];
      C[(size_t)gr*D3_ + gc + 1]   = acc[mt][nt][1] + bias[gc+1];
      C[(size_t)(gr+8)*D3_ + gc]   = acc[mt][nt][2] + bias[gc];
      C[(size_t)(gr+8)*D3_ + gc+1] = acc[mt][nt][3] + bias[gc+1];
    }
  }
}

// persistent recurrence: 512 thr = 12 MMA warps (wk=warp&3, wn=warp>>2) + 4 loader warps.
// Ready handshake: monotone shared counters rdy[c] (st.release by loader after CP_WAIT,
// ld.acquire spin by MMA warps) — phase-loss/deadlock impossible by construction.
// Free bars 9+c (128: 96 MMA arrive + 32 loader sync). Bar 13 partials (384), 14 gate (256).
#define HS_STRIDE 1032
#define OFF_WS   66048
#define OFF_XG   (OFF_WS + 99072)
#define OFF_HGP  (OFF_XG + 12288)
#define OFF_BHH  (OFF_HGP + 50176)
#define OFF_RDY  (OFF_BHH + 192)
#define RNN_SMEM (OFF_RDY + 128)

__global__ __launch_bounds__(512, 1) void k_rnn(int layer,
    const float* __restrict__ Whh_f, const float* __restrict__ Whh_b,
    const float* __restrict__ bhh_f, const float* __restrict__ bhh_b) {
  extern __shared__ char smem_raw[];
  __nv_bfloat16* hs  = (__nv_bfloat16*)smem_raw;                 // [32][1032]
  __nv_bfloat16* Ws  = (__nv_bfloat16*)(smem_raw + OFF_WS);      // [48][1032]
  float*         xg_s= (float*)(smem_raw + OFF_XG);              // [2][32][48]
  float*         hgp = (float*)(smem_raw + OFF_HGP);             // [2][32][196]
  float*         bhh_s=(float*)(smem_raw + OFF_BHH);             // [48]
  unsigned*      rdy = (unsigned*)(smem_raw + OFF_RDY);          // [4] stride 8 words

  int stack = blockIdx.x >> 6;
  int blk   = blockIdx.x & 63;
  int cgb   = blk * 16;
  const float* Whh = (stack ? Whh_b : Whh_f) + (size_t)layer*D3_*D_;
  const float* xg = g_xg[stack];
  const float* bhh = (stack ? bhh_b : bhh_f) + (size_t)layer*D3_;
  __nv_bfloat16* ys = stack ? g_yb_bf : g_yf_bf;

  int tid = threadIdx.x, lane = tid&31, warp = tid>>5;
  int wk = warp & 3, wn = warp >> 2;
  int tg = lane>>2, tc = lane&3;

  for (int i = tid; i < 12288; i += 512) {
    int row = i >> 8, q4 = (i & 255) * 4;
    size_t grow = (size_t)((row >> 4)*D_ + cgb + (row & 15));
    float4 v = *(const float4*)&Whh[grow*D_ + q4];
    __nv_bfloat16 b4[4] = { __float2bfloat16(v.x), __float2bfloat16(v.y),
                            __float2bfloat16(v.z), __float2bfloat16(v.w) };
    *(uint2*)&Ws[row*HS_STRIDE + q4] = *(uint2*)b4;
  }
  for (int i = tid; i < 48; i += 512)
    bhh_s[i] = bhh[(i>>4)*D_ + cgb + (i&15)];
  {
    uint4 z = make_uint4(0,0,0,0);
    for (int i = tid; i < 4096; i += 512) {
      int b = i >> 7, c8 = (i & 127) * 8;
      *(uint4*)&hs[b*HS_STRIDE + c8] = z;
    }
  }
  if (tid < 384) {       // xg(t=0) into buffer 0
    int pb = tid / 12, prem = tid % 12, pg = prem >> 2, pq = prem & 3;
    uint4 v = *(const uint4*)&xg[(size_t)pb*D3_ + (size_t)pg*D_ + cgb + pq*4];
    *(uint4*)&xg_s[pb*48 + pg*16 + pq*4] = v;
  }
  if (tid < 4) rdy[tid*8] = 0;
  if (tid == 0) g_flag[stack][blk][0] = 0;
  gridbar2(stack, 64);

  unsigned hs_sm = (unsigned)__cvta_generic_to_shared(hs);
  unsigned ws_sm = (unsigned)__cvta_generic_to_shared(Ws);
  unsigned xg_sm = (unsigned)__cvta_generic_to_shared(xg_s);
  unsigned rdy_sm = (unsigned)__cvta_generic_to_shared(rdy);

  if (warp >= 12) {
    // ---------------- loader warp c ----------------
    int c = warp - 12;
    unsigned rc = rdy_sm + 32u*c;
    const size_t stk = (size_t)stack*B_*D_;
    int q = c*32 + lane;
    size_t xsrcoff[3]; unsigned xdstoff[3];
    #pragma unroll
    for (int k = 0; k < 3; k++) {
      int u = q*3 + k;
      int b = u / 12, rem = u % 12, g = rem >> 2, q4 = rem & 3;
      xsrcoff[k] = (size_t)b*D3_ + (size_t)g*D_ + cgb + q4*4;
      xdstoff[k] = 4u*(unsigned)(b*48 + g*16 + q4*4);
    }
    for (int j = 0; j < T_ - 1; j++) {
      BAR_SYNC(9 + c, 128);                       // hs(t=j) consumed by group c
      const __nv_bfloat16* hin = g_hbf[(j + 1) & 1] + stk;
      unsigned want = (unsigned)(j + 1);
      unsigned base = (unsigned)(j * 4);
      {
        const float* xsrc = xg + (size_t)(j + 1)*B_*D3_;
        unsigned xdst = xg_sm + (unsigned)(((j + 1) & 1) * 6144);
        cpasync16(xdst + xdstoff[0], xsrc + xsrcoff[0]);
        cpasync16(xdst + xdstoff[1], xsrc + xsrcoff[1]);
        cpasync16(xdst + xdstoff[2], xsrc + xsrcoff[2]);
      }
      #define POLLS(s) do { \
        const unsigned* fps = &g_flag[stack][c*16 + (s)*4 + (lane & 3)][0]; \
        unsigned v = (lane < 4) ? ld_acq(fps) : 0xffffffffu; \
        while (!__all_sync(0xffffffffu, v >= want)) \
          v = (lane < 4) ? ld_acq(fps) : 0xffffffffu; \
      } while (0)
      #define ISSUES(s) do { \
        int basec = c*256 + (s)*64; \
        _Pragma("unroll") \
        for (int it2 = 0; it2 < 8; it2++) { \
          int i2 = lane + it2*32; \
          int b2 = i2 >> 3, q2 = (i2 & 7)*8; \
          cpasync16(hs_sm + 2u*(unsigned)(b2*HS_STRIDE + basec + q2), \
                    hin + (size_t)b2*D_ + basec + q2); \
        } \
        CP_COMMIT(); \
      } while (0)
      #define PUB(n) do { __syncwarp(); if (lane == 0) st_rel_sh(rc, base + (n)); } while (0)
      POLLS(0); ISSUES(0);
      POLLS(1); ISSUES(1);
      CP_WAIT(1); PUB(1);
      POLLS(2); ISSUES(2);
      CP_WAIT(1); PUB(2);
      POLLS(3); ISSUES(3);
      CP_WAIT(1); PUB(3);
      CP_WAIT(0); PUB(4);
      #undef POLLS
      #undef ISSUES
      #undef PUB
    }
    BAR_SYNC(9 + c, 128);                         // balance t=T-1 free arrivals
  } else {
    // ---------------- MMA (+gate) warps ----------------
    int gb = tid >> 3, jp = tid & 7;              // gate: batch gb, cols 2jp, 2jp+1
    unsigned* myflag = &g_flag[stack][blk][0];
    unsigned rwk = rdy_sm + 32u*wk;

    unsigned aBase0 = hs_sm + 2u*((lane&15)*HS_STRIDE + ((lane>>4)*8) + wk*256);
    unsigned aBase1 = aBase0 + 2u*16*HS_STRIDE;
    unsigned bBase  = ws_sm + 2u*((wn*16 + (lane&7) + ((lane>>4)*8))*HS_STRIDE
                                + (((lane>>3)&1)*8) + wk*256);
    float hp0 = 0.f, hp1 = 0.f;

    for (int t = 0; t < T_; t++) {
      int buf = t & 1;
      float* xgb = xg_s + buf*1536;
      float* hgb = hgp  + buf*6272;

      float acc[2][2][4];
      #pragma unroll
      for (int i=0;i<2;i++)
        #pragma unroll
        for (int j2=0;j2<2;j2++)
          #pragma unroll
          for (int q=0;q<4;q++) acc[i][j2][q]=0.f;

      #pragma unroll
      for (int s = 0; s < 4; s++) {
        if (t > 0) {
          unsigned tgt = (unsigned)((t - 1)*4 + s + 1);
          while (ld_acq_sh(rwk) < tgt) { }
        }
        unsigned a0A = aBase0 + 128u*s, a1A = aBase1 + 128u*s, bA = bBase + 128u*s;
        #pragma unroll
        for (int kt = 0; kt < 4; kt++) {
          unsigned fa0[4], fa1[4], fb[4];
          ldsm4(fa0, a0A); ldsm4(fa1, a1A); ldsm4(fb, bA);
          MMA_BF16(acc[0][0], fa0[0],fa0[1],fa0[2],fa0[3], fb[0], fb[1]);
          MMA_BF16(acc[0][1], fa0[0],fa0[1],fa0[2],fa0[3], fb[2], fb[3]);
          MMA_BF16(acc[1][0], fa1[0],fa1[1],fa1[2],fa1[3], fb[0], fb[1]);
          MMA_BF16(acc[1][1], fa1[0],fa1[1],fa1[2],fa1[3], fb[2], fb[3]);
          a0A += 32; a1A += 32; bA += 32;
        }
      }
      BAR_ARR(9 + wk, 128);                       // hs(t) consumed

      #pragma unroll
      for (int mf = 0; mf < 2; mf++) {
        #pragma unroll
        for (int nf = 0; nf < 2; nf++) {
          int r = mf*16 + tg;
          int col = wn*16 + nf*8 + 2*tc;
          hgb[r*196 + col*4 + wk]         = acc[mf][nf][0];
          hgb[r*196 + (col+1)*4 + wk]     = acc[mf][nf][1];
          hgb[(r+8)*196 + col*4 + wk]     = acc[mf][nf][2];
          hgb[(r+8)*196 + (col+1)*4 + wk] = acc[mf][nf][3];
        }
      }
      if (warp < 8) {
        BAR_SYNC(13, 384);
        __nv_bfloat16* hout = g_hbf[buf ^ 1] + (size_t)stack*B_*D_;
        #pragma unroll
        for (int half = 0; half < 2; half++) {
          int j = 2*jp + half;
          float4 pr = *(const float4*)&hgb[gb*196 + j*4];
          float4 pz = *(const float4*)&hgb[gb*196 + (16 + j)*4];
          float4 pn = *(const float4*)&hgb[gb*196 + (32 + j)*4];
          float xr = xgb[gb*48 + j];
          float xz = xgb[gb*48 + 16 + j];
          float xn = xgb[gb*48 + 32 + j];
          float hr = bhh_s[j]      + ((pr.x + pr.y) + (pr.z + pr.w));
          float hz = bhh_s[16 + j] + ((pz.x + pz.y) + (pz.z + pz.w));
          float hn = bhh_s[32 + j] + ((pn.x + pn.y) + (pn.z + pn.w));
          float r  = 1.f/(1.f + __expf(-(xr+hr)));
          float z  = 1.f/(1.f + __expf(-(xz+hz)));
          float nn = fast_tanh(xn + r*hn);
          float hprev = half ? hp1 : hp0;
          float hnew = (1.f - z)*nn + z*hprev;
          if (half) hp1 = hnew; else hp0 = hnew;
        }
        __nv_bfloat162 pk;
        pk.x = __float2bfloat16(hp0);
        pk.y = __float2bfloat16(hp1);
        *(__nv_bfloat162*)&hout[(size_t)gb*D_ + cgb + 2*jp] = pk;
        BAR_SYNC(14, 256);
        if (tid == 0) st_rel(myflag, (unsigned)(t + 1));
        *(__nv_bfloat162*)&ys[((size_t)t*B_ + gb)*D_ + cgb + 2*jp] = pk;
      } else {
        BAR_ARR(13, 384);
      }
    }
  }
}

__global__ __launch_bounds__(128) void k_out1(const float* __restrict__ Wo, const float* __restrict__ bo) {
  int row = blockIdx.x;
  int tid = threadIdx.x;
  float acc = 0.f;
  for (int d = tid; d < D_; d += 128)
    acc += (__bfloat162float(g_yf_bf[(size_t)row*D_+d]) +
            __bfloat162float(g_yb_bf[(size_t)row*D_+d])) * Wo[d];
  #pragma unroll
  for (int o = 16; o; o >>= 1) acc += __shfl_xor_sync(0xffffffffu, acc, o);
  __shared__ float ws[4];
  if ((tid & 31) == 0) ws[tid>>5] = acc;
  __syncthreads();
  if (tid == 0) {
    float s = ws[0]+ws[1]+ws[2]+ws[3] + bo[0];
    g_outvals[row] = 1.f/(1.f + expf(-s));
  }
}

__global__ void k_out2(float* out) {
  __shared__ float sm[256];
  int tid = threadIdx.x;
  float s = 0.f;
  for (int i = tid; i < TB_; i += 256) s += g_outvals[i];
  sm[tid] = s;
  __syncthreads();
  for (int o = 128; o; o >>= 1) { if (tid < o) sm[tid] += sm[tid+o]; __syncthreads(); }
  if (tid == 0) out[0] = sm[0] / (float)TB_;
}

extern "C" void kernel_launch(void* const* d_in, const int* in_sizes, int n_in,
                              void* d_out, int out_size) {
  (void)in_sizes; (void)n_in; (void)out_size;
  const float* input = (const float*)d_in[0];
  const float* cond  = (const float*)d_in[1];
  const float* Wc    = (const float*)d_in[2];
  const float* bc    = (const float*)d_in[3];
  const float* Wi    = (const float*)d_in[4];
  const float* bi    = (const float*)d_in[5];
  const float* Wih_f = (const float*)d_in[6];
  const float* Whh_f = (const float*)d_in[7];
  const float* bih_f = (const float*)d_in[8];
  const float* bhh_f = (const float*)d_in[9];
  const float* Wih_b = (const float*)d_in[10];
  const float* Whh_b = (const float*)d_in[11];
  const float* bih_b = (const float*)d_in[12];
  const float* bhh_b = (const float*)d_in[13];
  const float* Wo    = (const float*)d_in[14];
  const float* bo    = (const float*)d_in[15];
  float* out = (float*)d_out;

  cudaFuncSetAttribute(k_rnn, cudaFuncAttributeMaxDynamicSharedMemorySize, RNN_SMEM);

  k_convw<<<4096, 256>>>(Wih_f, Wih_b);
  k_proj<<<256, 256>>>(input, cond, Wc, bc, Wi, bi);
  for (int l = 0; l < L_; l++) {
    k_gemm<<<dim3(48, 64, 2), 256>>>(l, bih_f, bih_b);
    k_rnn<<<NCTA_, 512, RNN_SMEM>>>(l, Whh_f, Whh_b, bhh_f, bhh_b);
  }
  k_out1<<<TB_, 128>>>(Wo, bo);
  k_out2<<<1, 256>>>(out);
}

// round 12
// speedup vs baseline: 1.1683x; 1.1644x over previous
#include <cuda_runtime.h>
#include <cuda_bf16.h>
#include <math.h>

#define B_  32
#define T_  256
#define D_  1024
#define D3_ 3072
#define TB_ 8192
#define L_  2
#define NCTA_ 128

__device__ __nv_bfloat16 g_Wih_bf[2*L_*D3_*D_];
__device__ __nv_bfloat16 g_x_bf [TB_*D_];
__device__ __nv_bfloat16 g_yf_bf[TB_*D_];
__device__ __nv_bfloat16 g_yb_bf[TB_*D_];
__device__ float         g_xg[2][TB_*D3_];
__device__ __nv_bfloat16 g_hbf[2][2*B_*D_];
__device__ float         g_outvals[TB_];

__device__ unsigned g_flag[2][64][32];
__device__ unsigned g_barc2[2*32];
__device__ unsigned g_barg2[2*32];

#define MMA_BF16(d, a0,a1,a2,a3, b0,b1) \
  asm volatile("mma.sync.aligned.m16n8k16.row.col.f32.bf16.bf16.f32 " \
    "{%0,%1,%2,%3},{%4,%5,%6,%7},{%8,%9},{%0,%1,%2,%3};\n" \
    : "+f"(d[0]), "+f"(d[1]), "+f"(d[2]), "+f"(d[3]) \
    : "r"(a0), "r"(a1), "r"(a2), "r"(a3), "r"(b0), "r"(b1))

__device__ __forceinline__ void ldsm4(unsigned* r, unsigned a) {
  asm volatile("ldmatrix.sync.aligned.m8n8.x4.shared.b16 {%0,%1,%2,%3}, [%4];"
    : "=r"(r[0]), "=r"(r[1]), "=r"(r[2]), "=r"(r[3]) : "r"(a));
}
__device__ __forceinline__ void cpasync16(unsigned dst, const void* src) {
  asm volatile("cp.async.cg.shared.global [%0], [%1], 16;" :: "r"(dst), "l"(src));
}
#define CP_COMMIT() asm volatile("cp.async.commit_group;" ::: "memory")
#define CP_WAIT(n)  asm volatile("cp.async.wait_group %0;" :: "n"(n) : "memory")
#define BAR_SYNC(id,cnt) asm volatile("bar.sync %0,%1;"::"r"(id),"r"(cnt):"memory")
#define BAR_ARR(id,cnt)  asm volatile("bar.arrive %0,%1;"::"r"(id),"r"(cnt):"memory")

__device__ __forceinline__ unsigned ld_acq(const unsigned* p) {
  unsigned v;
  asm volatile("ld.acquire.gpu.global.u32 %0, [%1];" : "=r"(v) : "l"(p));
  return v;
}
__device__ __forceinline__ void st_rel(unsigned* p, unsigned v) {
  asm volatile("st.release.gpu.global.u32 [%0], %1;" :: "l"(p), "r"(v));
}
__device__ __forceinline__ unsigned ld_acq_sh(unsigned a) {
  unsigned v;
  asm volatile("ld.acquire.cta.shared.u32 %0, [%1];" : "=r"(v) : "r"(a));
  return v;
}
__device__ __forceinline__ void st_rel_sh(unsigned a, unsigned v) {
  asm volatile("st.release.cta.shared.u32 [%0], %1;" :: "r"(a), "r"(v));
}
__device__ __forceinline__ float fast_tanh(float x) {
  float xc = fminf(fmaxf(x, -30.f), 30.f);
  float e = __expf(-2.f*xc);
  return (1.f - e) * __frcp_rn(1.f + e);
}
__device__ __forceinline__ void gridbar2(int s, unsigned nc) {
  __syncthreads();
  if (threadIdx.x == 0) {
    __threadfence();
    volatile unsigned* genp = (volatile unsigned*)&g_barg2[s*32];
    unsigned gen = *genp;
    if (atomicAdd(&g_barc2[s*32], 1u) == nc - 1u) {
      g_barc2[s*32] = 0;
      __threadfence();
      *genp = gen + 1;
    } else {
      while (*genp == gen) { }
      __threadfence();
    }
  }
  __syncthreads();
}

__global__ void k_convw(const float* __restrict__ Wih_f, const float* __restrict__ Wih_b) {
  const int N = L_*D3_*D_;
  for (int i = blockIdx.x*blockDim.x + threadIdx.x; i < N; i += gridDim.x*blockDim.x) {
    g_Wih_bf[i]     = __float2bfloat16(Wih_f[i]);
    g_Wih_bf[N + i] = __float2bfloat16(Wih_b[i]);
  }
}

__global__ __launch_bounds__(256) void k_proj(const float* __restrict__ input, const float* __restrict__ cond,
    const float* __restrict__ Wc, const float* __restrict__ bc,
    const float* __restrict__ Wi, const float* __restrict__ bi) {
  int t = blockIdx.x;
  int tid = threadIdx.x;
  __shared__ float cond_s[B_][80];
  __shared__ float in_s[B_][72];
  __shared__ float wbuf[64][80];
  __shared__ float bias_s[64];
  for (int i = tid; i < B_*80; i += 256) {
    int b = i / 80, j = i % 80;
    cond_s[b][j] = cond[((size_t)b*T_ + t)*80 + j];
  }
  for (int i = tid; i < B_*72; i += 256) {
    int b = i / 72, j = i % 72;
    in_s[b][j] = input[((size_t)b*T_ + t)*72 + j];
  }
  __syncthreads();
  for (int chunk = 0; chunk < 16; chunk++) {
    int dbase = chunk*64;
    int width = (dbase < 512) ? 80 : 72;
    const float* Wsrc = (dbase < 512) ? (Wc + (size_t)dbase*80) : (Wi + (size_t)(dbase-512)*72);
    for (int i = tid; i < 64*width; i += 256) wbuf[i/width][i%width] = Wsrc[i];
    if (tid < 64) bias_s[tid] = (dbase < 512) ? bc[dbase+tid] : bi[dbase-512+tid];
    __syncthreads();
    for (int i = tid; i < B_*64; i += 256) {
      int b = i & 31, dd = i >> 5;
      const float* act = (dbase < 512) ? &cond_s[b][0] : &in_s[b][0];
      float a = bias_s[dd];
      const float* w = &wbuf[dd][0];
      #pragma unroll 8
      for (int j = 0; j < width; j++) a += w[j]*act[j];
      a = fmaxf(a, 0.f);
      g_x_bf[((size_t)t*B_ + b)*D_ + dbase + dd] = __float2bfloat16(a);
    }
    __syncthreads();
  }
}

// ---------------- xg = A @ Wih^T + bih : 128x128 tiles, 512 thr, 3-stage cp.async ----------------
#define GS 72                 // smem row stride (elements)
#define GSTAGE (128*GS)       // elements per stage per operand
#define GEMM_SMEM (2*3*GSTAGE*2)   // 110592 bytes

__global__ __launch_bounds__(512) void k_gemm(int layer,
    const float* __restrict__ bih_f, const float* __restrict__ bih_b) {
  extern __shared__ __nv_bfloat16 gsm[];
  __nv_bfloat16* As = gsm;                 // [3][128][GS]
  __nv_bfloat16* Bs = gsm + 3*GSTAGE;      // [3][128][GS]

  int dir = blockIdx.z;
  const __nv_bfloat16* A = (layer == 0) ? g_x_bf : (dir ? g_yb_bf : g_yf_bf);
  const __nv_bfloat16* W = g_Wih_bf + (size_t)(dir*L_ + layer)*D3_*D_;
  const float* bias = (dir ? bih_b : bih_f) + (size_t)layer*D3_;
  float* C = g_xg[dir];
  int n0 = blockIdx.x*128, m0 = blockIdx.y*128;

  int tid = threadIdx.x, lane = tid&31, warp = tid>>5;
  int wm = warp & 3, wn = warp >> 2;       // 4x4 warp grid, warp tile m32 x n32
  int tg = lane>>2, tc = lane&3;

  unsigned as_sm = (unsigned)__cvta_generic_to_shared(As);
  unsigned bs_sm = (unsigned)__cvta_generic_to_shared(Bs);

  // load mapping: 1024 16B-units per operand per stage; 2 per thread
  int r0 = tid >> 2, q0 = (tid & 3) * 2;   // unit pairs: rows tid>>2, q (tid&3)*2, +1
  const __nv_bfloat16* aSrc = A + (size_t)(m0 + r0)*D_ + q0*8;
  const __nv_bfloat16* bSrc = W + (size_t)(n0 + r0)*D_ + q0*8;
  unsigned aDst = as_sm + 2u*(unsigned)(r0*GS + q0*8);
  unsigned bDst = bs_sm + 2u*(unsigned)(r0*GS + q0*8);

  #define GLOAD(kc, st) do { \
    unsigned off = 2u*(unsigned)((st)*GSTAGE); \
    const __nv_bfloat16* ap = aSrc + (kc)*64; \
    const __nv_bfloat16* bp = bSrc + (kc)*64; \
    cpasync16(aDst + off,       ap); \
    cpasync16(aDst + off + 16u, ap + 8); \
    cpasync16(bDst + off,       bp); \
    cpasync16(bDst + off + 16u, bp + 8); \
    CP_COMMIT(); \
  } while (0)

  GLOAD(0, 0);
  GLOAD(1, 1);

  float acc[2][4][4];
  #pragma unroll
  for (int i=0;i<2;i++)
    #pragma unroll
    for (int j=0;j<4;j++)
      #pragma unroll
      for (int q=0;q<4;q++) acc[i][j][q]=0.f;

  unsigned aB = as_sm + 2u*(unsigned)((wm*32 + (lane&15))*GS + (lane>>4)*8);
  unsigned bB = bs_sm + 2u*(unsigned)((wn*32 + (lane&7) + ((lane>>4)*8))*GS + ((lane>>3)&1)*8);

  for (int kc = 0; kc < 16; kc++) {
    if (kc == 15) { CP_WAIT(0); } else { CP_WAIT(1); }
    __syncthreads();
    if (kc + 2 < 16) GLOAD(kc + 2, (kc + 2) % 3);

    unsigned soff = 2u*(unsigned)((kc % 3)*GSTAGE);
    unsigned a0A = aB + soff, a1A = a0A + 2u*16*GS;
    unsigned b0A = bB + soff, b1A = b0A + 2u*16*GS;
    #pragma unroll
    for (int k16 = 0; k16 < 4; k16++) {
      unsigned fa0[4], fa1[4], fb0[4], fb1[4];
      ldsm4(fa0, a0A); ldsm4(fa1, a1A);
      ldsm4(fb0, b0A); ldsm4(fb1, b1A);
      MMA_BF16(acc[0][0], fa0[0],fa0[1],fa0[2],fa0[3], fb0[0], fb0[1]);
      MMA_BF16(acc[0][1], fa0[0],fa0[1],fa0[2],fa0[3], fb0[2], fb0[3]);
      MMA_BF16(acc[0][2], fa0[0],fa0[1],fa0[2],fa0[3], fb1[0], fb1[1]);
      MMA_BF16(acc[0][3], fa0[0],fa0[1],fa0[2],fa0[3], fb1[2], fb1[3]);
      MMA_BF16(acc[1][0], fa1[0],fa1[1],fa1[2],fa1[3], fb0[0], fb0[1]);
      MMA_BF16(acc[1][1], fa1[0],fa1[1],fa1[2],fa1[3], fb0[2], fb0[3]);
      MMA_BF16(acc[1][2], fa1[0],fa1[1],fa1[2],fa1[3], fb1[0], fb1[1]);
      MMA_BF16(acc[1][3], fa1[0],fa1[1],fa1[2],fa1[3], fb1[2], fb1[3]);
      a0A += 32; a1A += 32; b0A += 32; b1A += 32;
    }
  }
  #undef GLOAD

  #pragma unroll
  for (int mf = 0; mf < 2; mf++) {
    #pragma unroll
    for (int nf = 0; nf < 4; nf++) {
      int gr = m0 + wm*32 + mf*16 + tg;
      int gc = n0 + wn*32 + nf*8 + 2*tc;
      float b0v = bias[gc], b1v = bias[gc+1];
      float2 v0 = make_float2(acc[mf][nf][0] + b0v, acc[mf][nf][1] + b1v);
      float2 v1 = make_float2(acc[mf][nf][2] + b0v, acc[mf][nf][3] + b1v);
      *(float2*)&C[(size_t)gr*D3_ + gc]     = v0;
      *(float2*)&C[(size_t)(gr+8)*D3_ + gc] = v1;
    }
  }
}

// persistent recurrence (unchanged from R11: monotone shared-counter handshake)
#define HS_STRIDE 1032
#define OFF_WS   66048
#define OFF_XG   (OFF_WS + 99072)
#define OFF_HGP  (OFF_XG + 12288)
#define OFF_BHH  (OFF_HGP + 50176)
#define OFF_RDY  (OFF_BHH + 192)
#define RNN_SMEM (OFF_RDY + 128)

__global__ __launch_bounds__(512, 1) void k_rnn(int layer,
    const float* __restrict__ Whh_f, const float* __restrict__ Whh_b,
    const float* __restrict__ bhh_f, const float* __restrict__ bhh_b) {
  extern __shared__ char smem_raw[];
  __nv_bfloat16* hs  = (__nv_bfloat16*)smem_raw;
  __nv_bfloat16* Ws  = (__nv_bfloat16*)(smem_raw + OFF_WS);
  float*         xg_s= (float*)(smem_raw + OFF_XG);
  float*         hgp = (float*)(smem_raw + OFF_HGP);
  float*         bhh_s=(float*)(smem_raw + OFF_BHH);
  unsigned*      rdy = (unsigned*)(smem_raw + OFF_RDY);

  int stack = blockIdx.x >> 6;
  int blk   = blockIdx.x & 63;
  int cgb   = blk * 16;
  const float* Whh = (stack ? Whh_b : Whh_f) + (size_t)layer*D3_*D_;
  const float* xg = g_xg[stack];
  const float* bhh = (stack ? bhh_b : bhh_f) + (size_t)layer*D3_;
  __nv_bfloat16* ys = stack ? g_yb_bf : g_yf_bf;

  int tid = threadIdx.x, lane = tid&31, warp = tid>>5;
  int wk = warp & 3, wn = warp >> 2;
  int tg = lane>>2, tc = lane&3;

  for (int i = tid; i < 12288; i += 512) {
    int row = i >> 8, q4 = (i & 255) * 4;
    size_t grow = (size_t)((row >> 4)*D_ + cgb + (row & 15));
    float4 v = *(const float4*)&Whh[grow*D_ + q4];
    __nv_bfloat16 b4[4] = { __float2bfloat16(v.x), __float2bfloat16(v.y),
                            __float2bfloat16(v.z), __float2bfloat16(v.w) };
    *(uint2*)&Ws[row*HS_STRIDE + q4] = *(uint2*)b4;
  }
  for (int i = tid; i < 48; i += 512)
    bhh_s[i] = bhh[(i>>4)*D_ + cgb + (i&15)];
  {
    uint4 z = make_uint4(0,0,0,0);
    for (int i = tid; i < 4096; i += 512) {
      int b = i >> 7, c8 = (i & 127) * 8;
      *(uint4*)&hs[b*HS_STRIDE + c8] = z;
    }
  }
  if (tid < 384) {
    int pb = tid / 12, prem = tid % 12, pg = prem >> 2, pq = prem & 3;
    uint4 v = *(const uint4*)&xg[(size_t)pb*D3_ + (size_t)pg*D_ + cgb + pq*4];
    *(uint4*)&xg_s[pb*48 + pg*16 + pq*4] = v;
  }
  if (tid < 4) rdy[tid*8] = 0;
  if (tid == 0) g_flag[stack][blk][0] = 0;
  gridbar2(stack, 64);

  unsigned hs_sm = (unsigned)__cvta_generic_to_shared(hs);
  unsigned ws_sm = (unsigned)__cvta_generic_to_shared(Ws);
  unsigned xg_sm = (unsigned)__cvta_generic_to_shared(xg_s);
  unsigned rdy_sm = (unsigned)__cvta_generic_to_shared(rdy);

  if (warp >= 12) {
    int c = warp - 12;
    unsigned rc = rdy_sm + 32u*c;
    const size_t stk = (size_t)stack*B_*D_;
    int q = c*32 + lane;
    size_t xsrcoff[3]; unsigned xdstoff[3];
    #pragma unroll
    for (int k = 0; k < 3; k++) {
      int u = q*3 + k;
      int b = u / 12, rem = u % 12, g = rem >> 2, q4 = rem & 3;
      xsrcoff[k] = (size_t)b*D3_ + (size_t)g*D_ + cgb + q4*4;
      xdstoff[k] = 4u*(unsigned)(b*48 + g*16 + q4*4);
    }
    for (int j = 0; j < T_ - 1; j++) {
      BAR_SYNC(9 + c, 128);
      const __nv_bfloat16* hin = g_hbf[(j + 1) & 1] + stk;
      unsigned want = (unsigned)(j + 1);
      unsigned base = (unsigned)(j * 4);
      {
        const float* xsrc = xg + (size_t)(j + 1)*B_*D3_;
        unsigned xdst = xg_sm + (unsigned)(((j + 1) & 1) * 6144);
        cpasync16(xdst + xdstoff[0], xsrc + xsrcoff[0]);
        cpasync16(xdst + xdstoff[1], xsrc + xsrcoff[1]);
        cpasync16(xdst + xdstoff[2], xsrc + xsrcoff[2]);
      }
      #define POLLS(s) do { \
        const unsigned* fps = &g_flag[stack][c*16 + (s)*4 + (lane & 3)][0]; \
        unsigned v = (lane < 4) ? ld_acq(fps) : 0xffffffffu; \
        while (!__all_sync(0xffffffffu, v >= want)) \
          v = (lane < 4) ? ld_acq(fps) : 0xffffffffu; \
      } while (0)
      #define ISSUES(s) do { \
        int basec = c*256 + (s)*64; \
        _Pragma("unroll") \
        for (int it2 = 0; it2 < 8; it2++) { \
          int i2 = lane + it2*32; \
          int b2 = i2 >> 3, q2 = (i2 & 7)*8; \
          cpasync16(hs_sm + 2u*(unsigned)(b2*HS_STRIDE + basec + q2), \
                    hin + (size_t)b2*D_ + basec + q2); \
        } \
        CP_COMMIT(); \
      } while (0)
      #define PUB(n) do { __syncwarp(); if (lane == 0) st_rel_sh(rc, base + (n)); } while (0)
      POLLS(0); ISSUES(0);
      POLLS(1); ISSUES(1);
      CP_WAIT(1); PUB(1);
      POLLS(2); ISSUES(2);
      CP_WAIT(1); PUB(2);
      POLLS(3); ISSUES(3);
      CP_WAIT(1); PUB(3);
      CP_WAIT(0); PUB(4);
      #undef POLLS
      #undef ISSUES
      #undef PUB
    }
    BAR_SYNC(9 + c, 128);
  } else {
    int gb = tid >> 3, jp = tid & 7;
    unsigned* myflag = &g_flag[stack][blk][0];
    unsigned rwk = rdy_sm + 32u*wk;

    unsigned aBase0 = hs_sm + 2u*((lane&15)*HS_STRIDE + ((lane>>4)*8) + wk*256);
    unsigned aBase1 = aBase0 + 2u*16*HS_STRIDE;
    unsigned bBase  = ws_sm + 2u*((wn*16 + (lane&7) + ((lane>>4)*8))*HS_STRIDE
                                + (((lane>>3)&1)*8) + wk*256);
    float hp0 = 0.f, hp1 = 0.f;

    for (int t = 0; t < T_; t++) {
      int buf = t & 1;
      float* xgb = xg_s + buf*1536;
      float* hgb = hgp  + buf*6272;

      float acc[2][2][4];
      #pragma unroll
      for (int i=0;i<2;i++)
        #pragma unroll
        for (int j2=0;j2<2;j2++)
          #pragma unroll
          for (int q=0;q<4;q++) acc[i][j2][q]=0.f;

      #pragma unroll
      for (int s = 0; s < 4; s++) {
        if (t > 0) {
          unsigned tgt = (unsigned)((t - 1)*4 + s + 1);
          while (ld_acq_sh(rwk) < tgt) { }
        }
        unsigned a0A = aBase0 + 128u*s, a1A = aBase1 + 128u*s, bA = bBase + 128u*s;
        #pragma unroll
        for (int kt = 0; kt < 4; kt++) {
          unsigned fa0[4], fa1[4], fb[4];
          ldsm4(fa0, a0A); ldsm4(fa1, a1A); ldsm4(fb, bA);
          MMA_BF16(acc[0][0], fa0[0],fa0[1],fa0[2],fa0[3], fb[0], fb[1]);
          MMA_BF16(acc[0][1], fa0[0],fa0[1],fa0[2],fa0[3], fb[2], fb[3]);
          MMA_BF16(acc[1][0], fa1[0],fa1[1],fa1[2],fa1[3], fb[0], fb[1]);
          MMA_BF16(acc[1][1], fa1[0],fa1[1],fa1[2],fa1[3], fb[2], fb[3]);
          a0A += 32; a1A += 32; bA += 32;
        }
      }
      BAR_ARR(9 + wk, 128);

      #pragma unroll
      for (int mf = 0; mf < 2; mf++) {
        #pragma unroll
        for (int nf = 0; nf < 2; nf++) {
          int r = mf*16 + tg;
          int col = wn*16 + nf*8 + 2*tc;
          hgb[r*196 + col*4 + wk]         = acc[mf][nf][0];
          hgb[r*196 + (col+1)*4 + wk]     = acc[mf][nf][1];
          hgb[(r+8)*196 + col*4 + wk]     = acc[mf][nf][2];
          hgb[(r+8)*196 + (col+1)*4 + wk] = acc[mf][nf][3];
        }
      }
      if (warp < 8) {
        BAR_SYNC(13, 384);
        __nv_bfloat16* hout = g_hbf[buf ^ 1] + (size_t)stack*B_*D_;
        #pragma unroll
        for (int half = 0; half < 2; half++) {
          int j = 2*jp + half;
          float4 pr = *(const float4*)&hgb[gb*196 + j*4];
          float4 pz = *(const float4*)&hgb[gb*196 + (16 + j)*4];
          float4 pn = *(const float4*)&hgb[gb*196 + (32 + j)*4];
          float xr = xgb[gb*48 + j];
          float xz = xgb[gb*48 + 16 + j];
          float xn = xgb[gb*48 + 32 + j];
          float hr = bhh_s[j]      + ((pr.x + pr.y) + (pr.z + pr.w));
          float hz = bhh_s[16 + j] + ((pz.x + pz.y) + (pz.z + pz.w));
          float hn = bhh_s[32 + j] + ((pn.x + pn.y) + (pn.z + pn.w));
          float r  = 1.f/(1.f + __expf(-(xr+hr)));
          float z  = 1.f/(1.f + __expf(-(xz+hz)));
          float nn = fast_tanh(xn + r*hn);
          float hprev = half ? hp1 : hp0;
          float hnew = (1.f - z)*nn + z*hprev;
          if (half) hp1 = hnew; else hp0 = hnew;
        }
        __nv_bfloat162 pk;
        pk.x = __float2bfloat16(hp0);
        pk.y = __float2bfloat16(hp1);
        *(__nv_bfloat162*)&hout[(size_t)gb*D_ + cgb + 2*jp] = pk;
        BAR_SYNC(14, 256);
        if (tid == 0) st_rel(myflag, (unsigned)(t + 1));
        *(__nv_bfloat162*)&ys[((size_t)t*B_ + gb)*D_ + cgb + 2*jp] = pk;
      } else {
        BAR_ARR(13, 384);
      }
    }
  }
}

__global__ __launch_bounds__(128) void k_out1(const float* __restrict__ Wo, const float* __restrict__ bo) {
  int row = blockIdx.x;
  int tid = threadIdx.x;
  float acc = 0.f;
  for (int d = tid; d < D_; d += 128)
    acc += (__bfloat162float(g_yf_bf[(size_t)row*D_+d]) +
            __bfloat162float(g_yb_bf[(size_t)row*D_+d])) * Wo[d];
  #pragma unroll
  for (int o = 16; o; o >>= 1) acc += __shfl_xor_sync(0xffffffffu, acc, o);
  __shared__ float ws[4];
  if ((tid & 31) == 0) ws[tid>>5] = acc;
  __syncthreads();
  if (tid == 0) {
    float s = ws[0]+ws[1]+ws[2]+ws[3] + bo[0];
    g_outvals[row] = 1.f/(1.f + expf(-s));
  }
}

__global__ void k_out2(float* out) {
  __shared__ float sm[256];
  int tid = threadIdx.x;
  float s = 0.f;
  for (int i = tid; i < TB_; i += 256) s += g_outvals[i];
  sm[tid] = s;
  __syncthreads();
  for (int o = 128; o; o >>= 1) { if (tid < o) sm[tid] += sm[tid+o]; __syncthreads(); }
  if (tid == 0) out[0] = sm[0] / (float)TB_;
}

extern "C" void kernel_launch(void* const* d_in, const int* in_sizes, int n_in,
                              void* d_out, int out_size) {
  (void)in_sizes; (void)n_in; (void)out_size;
  const float* input = (const float*)d_in[0];
  const float* cond  = (const float*)d_in[1];
  const float* Wc    = (const float*)d_in[2];
  const float* bc    = (const float*)d_in[3];
  const float* Wi    = (const float*)d_in[4];
  const float* bi    = (const float*)d_in[5];
  const float* Wih_f = (const float*)d_in[6];
  const float* Whh_f = (const float*)d_in[7];
  const float* bih_f = (const float*)d_in[8];
  const float* bhh_f = (const float*)d_in[9];
  const float* Wih_b = (const float*)d_in[10];
  const float* Whh_b = (const float*)d_in[11];
  const float* bih_b = (const float*)d_in[12];
  const float* bhh_b = (const float*)d_in[13];
  const float* Wo    = (const float*)d_in[14];
  const float* bo    = (const float*)d_in[15];
  float* out = (float*)d_out;

  cudaFuncSetAttribute(k_rnn, cudaFuncAttributeMaxDynamicSharedMemorySize, RNN_SMEM);
  cudaFuncSetAttribute(k_gemm, cudaFuncAttributeMaxDynamicSharedMemorySize, GEMM_SMEM);

  k_convw<<<4096, 256>>>(Wih_f, Wih_b);
  k_proj<<<256, 256>>>(input, cond, Wc, bc, Wi, bi);
  for (int l = 0; l < L_; l++) {
    k_gemm<<<dim3(24, 64, 2), 512, GEMM_SMEM>>>(l, bih_f, bih_b);
    k_rnn<<<NCTA_, 512, RNN_SMEM>>>(l, Whh_f, Whh_b, bhh_f, bhh_b);
  }
  k_out1<<<TB_, 128>>>(Wo, bo);
  k_out2<<<1, 256>>>(out);
}